// round 4
// baseline (speedup 1.0000x reference)
#include <cuda_runtime.h>
#include <math.h>

#define BB 32
#define CC 64
#define LL 512
#define VV 8192
#define NTOK_MAX (BB*LL)      /* 16384 */
#define NELEM (BB*CC*LL)      /* 1048576 */
#define TBTOK 16

// ---------------- device scratch (no malloc allowed) ----------------
__device__ float g_cbn[VV*CC];            // normalized codebook, 2MB
__device__ float g_frest[NELEM];          // residual, 4MB
__device__ float g_fhat[NELEM];           // reconstruction, 4MB
__device__ float g_rest_tok[NTOK_MAX*CC]; // downsampled+normalized tokens
__device__ int   g_idx[NTOK_MAX];         // selected codes
__device__ float g_pval[NTOK_MAX*64];     // per-vocab-split partial best val
__device__ int   g_pidx[NTOK_MAX*64];     // per-vocab-split partial best idx
__device__ float g_loss;                  // sum of squared err accum

// ---------------- codebook row-normalize (IEEE sqrt/div, fast-math-proof) ----
__global__ void normalize_cb_kernel(const float* __restrict__ ew) {
    int row = blockIdx.x;
    int lane = threadIdx.x;                 // 32 threads, 2 floats each
    float2 v = reinterpret_cast<const float2*>(ew + row*CC)[lane];
    float ss = v.x*v.x + v.y*v.y;
    #pragma unroll
    for (int off = 16; off > 0; off >>= 1)
        ss += __shfl_xor_sync(0xffffffffu, ss, off);
    float den = fmaxf(__fsqrt_rn(ss), 1e-12f);
    float2 o;
    o.x = __fdiv_rn(v.x, den);
    o.y = __fdiv_rn(v.y, den);
    reinterpret_cast<float2*>(g_cbn + row*CC)[lane] = o;
}

// ---------------- query token row-normalize (replicates reference bits) ----
// one warp per token; 8 tokens per 256-thread block
__global__ void normalize_tok_kernel(int ntok) {
    int t = blockIdx.x*8 + (threadIdx.x >> 5);
    if (t >= ntok) return;
    int lane = threadIdx.x & 31;
    float2* p = reinterpret_cast<float2*>(g_rest_tok + t*CC);
    float2 v = p[lane];
    float ss = v.x*v.x + v.y*v.y;
    #pragma unroll
    for (int off = 16; off > 0; off >>= 1)
        ss += __shfl_xor_sync(0xffffffffu, ss, off);
    float den = fmaxf(__fsqrt_rn(ss), 1e-12f);
    float2 o;
    o.x = __fdiv_rn(v.x, den);
    o.y = __fdiv_rn(v.y, den);
    p[lane] = o;
}

// ---------------- init residual / fhat / loss ----------------
__global__ void init_kernel(const float* __restrict__ f) {
    int i = blockIdx.x*256 + threadIdx.x;
    if (i < NELEM) { g_frest[i] = f[i]; g_fhat[i] = 0.f; }
    if (i == 0) g_loss = 0.f;
}

// ---------------- area downsample f_rest[B,C,L] -> tokens [B*s, C] ----------------
__global__ void downsample_kernel(int s, int r) {
    int gid = blockIdx.x*256 + threadIdx.x;
    int total = BB * s * CC;
    if (gid >= total) return;
    int c = gid & 63;
    int t = gid >> 6;
    int b = t / s, p = t - b*s;
    const float* src = g_frest + (b*CC + c)*LL + p*r;
    float sum = 0.f;
    for (int j = 0; j < r; ++j) sum += src[j];
    g_rest_tok[t*CC + c] = sum * (1.0f / (float)r);   // r is a power of two -> exact scale
}

// ---------------- cosine argmax: 16 tokens/block x vocab chunk ----------------
__global__ void __launch_bounds__(256, 2) argmax_kernel(int ntok, int chunk) {
    __shared__ __align__(16) float tok[TBTOK][CC];
    __shared__ float sval[8][TBTOK];
    __shared__ int   sidx[8][TBTOK];
    int t0 = blockIdx.x * TBTOK;
    for (int i = threadIdx.x; i < TBTOK*CC; i += 256) {
        int t = i >> 6, c = i & 63;
        int tg = t0 + t;
        tok[t][c] = (tg < ntok) ? g_rest_tok[tg*CC + c] : 0.f;
    }
    __syncthreads();

    float best[TBTOK]; int bidx[TBTOK];
    #pragma unroll
    for (int t = 0; t < TBTOK; ++t) { best[t] = -1e30f; bidx[t] = 0; }

    int vstart = blockIdx.y * chunk;
    int vend   = vstart + chunk;
    for (int v = vstart + threadIdx.x; v < vend; v += 256) {
        const float4* row = reinterpret_cast<const float4*>(g_cbn + v*CC);
        float4 rr[16];
        #pragma unroll
        for (int j = 0; j < 16; ++j) rr[j] = row[j];
        #pragma unroll
        for (int t = 0; t < TBTOK; ++t) {
            const float4* tk = reinterpret_cast<const float4*>(&tok[t][0]);
            // 4-lane vertical accumulate + pairwise horizontal (SIMD-natural order)
            float ax = 0.f, ay = 0.f, az = 0.f, aw = 0.f;
            #pragma unroll
            for (int j = 0; j < 16; ++j) {
                float4 tv = tk[j];
                ax = fmaf(rr[j].x, tv.x, ax);
                ay = fmaf(rr[j].y, tv.y, ay);
                az = fmaf(rr[j].z, tv.z, az);
                aw = fmaf(rr[j].w, tv.w, aw);
            }
            float d = (ax + ay) + (az + aw);
            if (d > best[t]) { best[t] = d; bidx[t] = v; }   // '>' keeps lowest idx
        }
    }

    int lane = threadIdx.x & 31, warp = threadIdx.x >> 5;
    #pragma unroll
    for (int t = 0; t < TBTOK; ++t) {
        float bv = best[t]; int bi = bidx[t];
        #pragma unroll
        for (int off = 16; off > 0; off >>= 1) {
            float ov = __shfl_down_sync(0xffffffffu, bv, off);
            int   oi = __shfl_down_sync(0xffffffffu, bi, off);
            if (ov > bv || (ov == bv && oi < bi)) { bv = ov; bi = oi; }
        }
        if (lane == 0) { sval[warp][t] = bv; sidx[warp][t] = bi; }
    }
    __syncthreads();
    if (threadIdx.x < TBTOK) {
        int t = threadIdx.x;
        float bv = sval[0][t]; int bi = sidx[0][t];
        #pragma unroll
        for (int w = 1; w < 8; ++w) {
            float ov = sval[w][t]; int oi = sidx[w][t];
            if (ov > bv || (ov == bv && oi < bi)) { bv = ov; bi = oi; }
        }
        int tg = t0 + t;
        if (tg < ntok) { g_pval[tg*64 + blockIdx.y] = bv; g_pidx[tg*64 + blockIdx.y] = bi; }
    }
}

// ---------------- reduce vocab splits per token ----------------
__global__ void reduce_kernel(int ntok, int vs) {
    int t = blockIdx.x*256 + threadIdx.x;
    if (t >= ntok) return;
    float bv = g_pval[t*64]; int bi = g_pidx[t*64];
    for (int sp = 1; sp < vs; ++sp) {
        float ov = g_pval[t*64 + sp]; int oi = g_pidx[t*64 + sp];
        if (ov > bv || (ov == bv && oi < bi)) { bv = ov; bi = oi; }
    }
    g_idx[t] = bi;
}

// ---------------- fused gather + upsample + Phi conv + residual update + loss ----------------
#define TL 64
#define PHI_SMEM_FLOATS (CC*(TL+2) + CC*193 + CC)
__global__ void __launch_bounds__(256) phi_update_kernel(
    const float* __restrict__ f, const float* __restrict__ ew,
    const float* __restrict__ phiw, const float* __restrict__ phib,
    int s, int pidx)
{
    extern __shared__ float sm[];
    float* tile = sm;                 // [64][66]
    float* ws   = sm + CC*(TL+2);     // [64][193]
    float* bs   = ws + CC*193;        // [64]

    int b  = blockIdx.x >> 3;
    int l0 = (blockIdx.x & 7) * TL;
    int tid = threadIdx.x;

    const float* wsrc = phiw + pidx*CC*CC*3;
    for (int i = tid; i < CC*192; i += 256) {
        int co = i / 192, rem = i - co*192;
        ws[co*193 + rem] = wsrc[i];
    }
    if (tid < CC) bs[tid] = phib[pidx*CC + tid];

    for (int i = tid; i < CC*(TL+2); i += 256) {
        int ci = i / (TL+2), j = i - ci*(TL+2);
        int l = l0 + j - 1;
        float v = 0.f;
        if (l >= 0 && l < LL) {
            int tokp = (l * s) >> 9;
            int code = g_idx[b*s + tokp];
            v = ew[code*CC + ci];
        }
        tile[ci*(TL+2) + j] = v;
    }
    __syncthreads();

    int co = tid & 63;
    int pbase = (tid >> 6) * 16;
    float acc[16];
    #pragma unroll
    for (int p = 0; p < 16; ++p) acc[p] = 0.f;

    for (int ci = 0; ci < CC; ++ci) {
        const float* wr = ws + co*193 + ci*3;
        float w0 = wr[0], w1 = wr[1], w2 = wr[2];
        const float* hr = tile + ci*(TL+2) + pbase;
        float h[18];
        #pragma unroll
        for (int j = 0; j < 18; ++j) h[j] = hr[j];
        #pragma unroll
        for (int p = 0; p < 16; ++p)
            acc[p] = fmaf(w0, h[p], fmaf(w1, h[p+1], fmaf(w2, h[p+2], acc[p])));
    }

    float ss = 0.f;
    float bb = bs[co];
    #pragma unroll
    for (int p = 0; p < 16; ++p) {
        int l = l0 + pbase + p;
        float hc = tile[co*(TL+2) + pbase + p + 1];
        float y = 0.5f*hc + 0.5f*(acc[p] + bb);
        int gi = (b*CC + co)*LL + l;
        float fh = g_fhat[gi] + y;
        g_fhat[gi] = fh;
        g_frest[gi] -= y;
        float d = fh - f[gi];
        ss = fmaf(d, d, ss);
    }

    #pragma unroll
    for (int off = 16; off > 0; off >>= 1)
        ss += __shfl_xor_sync(0xffffffffu, ss, off);
    __shared__ float red[8];
    int lane = tid & 31, warp = tid >> 5;
    if (lane == 0) red[warp] = ss;
    __syncthreads();
    if (tid == 0) {
        float tot = 0.f;
        #pragma unroll
        for (int w = 0; w < 8; ++w) tot += red[w];
        atomicAdd(&g_loss, tot);
    }
}

// ---------------- finalize: write f_hat and loss ----------------
__global__ void final_kernel(float* __restrict__ out, int out_size) {
    int i = blockIdx.x*256 + threadIdx.x;
    if (i >= out_size) return;
    if (i < NELEM)       out[i] = g_fhat[i];
    else if (i == NELEM) out[i] = g_loss * (1.25f / (10.0f * (float)NELEM));
    else                 out[i] = 0.f;
}

// ---------------- launch ----------------
extern "C" void kernel_launch(void* const* d_in, const int* in_sizes, int n_in,
                              void* d_out, int out_size) {
    // Bind inputs BY ELEMENT COUNT (pairwise distinct -> ordering-immune)
    const float* f    = nullptr;
    const float* ew   = nullptr;
    const float* phiw = nullptr;
    const float* phib = nullptr;
    for (int i = 0; i < n_in; ++i) {
        switch (in_sizes[i]) {
            case 1048576: f    = (const float*)d_in[i]; break;
            case 524288:  ew   = (const float*)d_in[i]; break;
            case 49152:   phiw = (const float*)d_in[i]; break;
            case 256:     phib = (const float*)d_in[i]; break;
            default: break;
        }
    }
    float* out = (float*)d_out;

    const int seg[10] = {1,2,4,8,16,32,64,128,256,512};

    // pmap: bit-exact float64 replication of np.linspace + np.argmin(first-wins)
    int pmap[10];
    {
        double start = 1.0 / 12.0;
        double stop  = 1.0 - 1.0 / 12.0;
        double delta = stop - start;
        double step  = delta / 3.0;
        double ticks[4];
        for (int i = 0; i < 4; ++i) ticks[i] = (double)i * step + start;
        ticks[3] = stop;
        for (int si = 0; si < 10; ++si) {
            double x = (double)si / 9.0;
            int best = 0;
            double bd = fabs(ticks[0] - x);
            for (int i = 1; i < 4; ++i) {
                double d = fabs(ticks[i] - x);
                if (d < bd) { bd = d; best = i; }
            }
            pmap[si] = best;
        }
    }

    cudaFuncSetAttribute(phi_update_kernel,
                         cudaFuncAttributeMaxDynamicSharedMemorySize,
                         PHI_SMEM_FLOATS * (int)sizeof(float));

    normalize_cb_kernel<<<VV, 32>>>(ew);
    init_kernel<<<(NELEM + 255)/256, 256>>>(f);

    for (int si = 0; si < 10; ++si) {
        int s = seg[si];
        int ntok = BB * s;
        int r = LL / s;

        int dtotal = ntok * CC;
        downsample_kernel<<<(dtotal + 255)/256, 256>>>(s, r);
        normalize_tok_kernel<<<(ntok + 7)/8, 256>>>(ntok);

        int vs = 1;
        if (ntok < 4096) { vs = 4096 / ntok; if (vs > 64) vs = 64; }
        int chunk = VV / vs;
        dim3 agrid((ntok + TBTOK - 1)/TBTOK, vs);
        argmax_kernel<<<agrid, 256>>>(ntok, chunk);

        reduce_kernel<<<(ntok + 255)/256, 256>>>(ntok, vs);

        phi_update_kernel<<<BB*8, 256, PHI_SMEM_FLOATS*(int)sizeof(float)>>>(
            f, ew, phiw, phib, s, pmap[si]);
    }

    final_kernel<<<(out_size + 255)/256, 256>>>(out, out_size);
}

// round 5
// speedup vs baseline: 7.3338x; 7.3338x over previous
#include <cuda_runtime.h>
#include <math.h>

#define BB 32
#define CC 64
#define LL 512
#define VV 8192
#define NTOK_MAX (BB*LL)      /* 16384 */
#define NELEM (BB*CC*LL)      /* 1048576 */
#define TBTOK 32              /* tokens per argmax block */
#define TR 128                /* codebook rows staged per tile */

// ---------------- device scratch (no malloc allowed) ----------------
__device__ float g_cbn[VV*CC];            // normalized codebook, 2MB
__device__ float g_frest[NELEM];          // residual, 4MB
__device__ float g_fhat[NELEM];           // reconstruction, 4MB
__device__ float g_rest_tok[NTOK_MAX*CC]; // downsampled+normalized tokens
__device__ int   g_idx[NTOK_MAX];         // selected codes
__device__ float g_pval[NTOK_MAX*64];     // per-vocab-split partial best val
__device__ int   g_pidx[NTOK_MAX*64];     // per-vocab-split partial best idx
__device__ float g_loss;                  // sum of squared err accum

// ---------------- codebook row-normalize (IEEE sqrt/div, fast-math-proof) ----
__global__ void normalize_cb_kernel(const float* __restrict__ ew) {
    int row = blockIdx.x;
    int lane = threadIdx.x;                 // 32 threads, 2 floats each
    float2 v = reinterpret_cast<const float2*>(ew + row*CC)[lane];
    float ss = v.x*v.x + v.y*v.y;
    #pragma unroll
    for (int off = 16; off > 0; off >>= 1)
        ss += __shfl_xor_sync(0xffffffffu, ss, off);
    float den = fmaxf(__fsqrt_rn(ss), 1e-12f);
    float2 o;
    o.x = __fdiv_rn(v.x, den);
    o.y = __fdiv_rn(v.y, den);
    reinterpret_cast<float2*>(g_cbn + row*CC)[lane] = o;
}

// ---------------- query token row-normalize (replicates reference bits) ----
__global__ void normalize_tok_kernel(int ntok) {
    int t = blockIdx.x*8 + (threadIdx.x >> 5);
    if (t >= ntok) return;
    int lane = threadIdx.x & 31;
    float2* p = reinterpret_cast<float2*>(g_rest_tok + t*CC);
    float2 v = p[lane];
    float ss = v.x*v.x + v.y*v.y;
    #pragma unroll
    for (int off = 16; off > 0; off >>= 1)
        ss += __shfl_xor_sync(0xffffffffu, ss, off);
    float den = fmaxf(__fsqrt_rn(ss), 1e-12f);
    float2 o;
    o.x = __fdiv_rn(v.x, den);
    o.y = __fdiv_rn(v.y, den);
    p[lane] = o;
}

// ---------------- init residual / fhat / loss ----------------
__global__ void init_kernel(const float* __restrict__ f) {
    int i = blockIdx.x*256 + threadIdx.x;
    if (i < NELEM) { g_frest[i] = f[i]; g_fhat[i] = 0.f; }
    if (i == 0) g_loss = 0.f;
}

// ---------------- area downsample f_rest[B,C,L] -> tokens [B*s, C] ----------------
__global__ void downsample_kernel(int s, int r) {
    int gid = blockIdx.x*256 + threadIdx.x;
    int total = BB * s * CC;
    if (gid >= total) return;
    int c = gid & 63;
    int t = gid >> 6;
    int b = t / s, p = t - b*s;
    const float* src = g_frest + (b*CC + c)*LL + p*r;
    float sum = 0.f;
    #pragma unroll 8
    for (int j = 0; j < r; ++j) sum += src[j];
    g_rest_tok[t*CC + c] = sum * (1.0f / (float)r);   // r power of two -> exact
}

// ---------------- cosine argmax: 32 tokens/block, codebook tiled via shared ----
// block 256: thread handles row (tid&127) of each 128-row tile, for 16 tokens
// of its half (g = tid>>7). Codebook tile XOR-swizzled in shared; coalesced fill.
// Per-(token,row) dot: 4 lane accumulators over j=0..15 then (ax+ay)+(az+aw)
// -- IDENTICAL summation order to the validated R4 kernel.
__global__ void __launch_bounds__(256) argmax_kernel(int ntok, int chunk) {
    __shared__ float4 s_tok[TBTOK*16];     // [token][j]            8KB
    __shared__ float4 s_cb[TR*16];         // swizzled tile        32KB
    __shared__ float  sval[8][16];
    __shared__ int    sidx[8][16];

    int tid = threadIdx.x;
    int t0  = blockIdx.x * TBTOK;

    // stage tokens (ntok is always a multiple of 32)
    for (int i = tid; i < TBTOK*16; i += 256) {
        int t = i >> 4, j = i & 15;
        s_tok[i] = reinterpret_cast<const float4*>(g_rest_tok + (t0 + t)*CC)[j];
    }

    int itg = tid & 127;        // row within tile
    int g   = tid >> 7;         // token half (16 tokens each)

    float best[16]; int bidx[16];
    #pragma unroll
    for (int t = 0; t < 16; ++t) { best[t] = -1e30f; bidx[t] = 0; }

    int vstart = blockIdx.y * chunk;
    int ntiles = chunk / TR;

    for (int tile = 0; tile < ntiles; ++tile) {
        __syncthreads();
        // coalesced fill of the 128-row tile, XOR-swizzled per row
        const float4* src = reinterpret_cast<const float4*>(g_cbn)
                          + (size_t)(vstart + tile*TR) * 16;
        for (int i = tid; i < TR*16; i += 256) {
            int row = i >> 4, j = i & 15;
            s_cb[(row << 4) | (j ^ (row & 15))] = src[i];
        }
        __syncthreads();

        // this thread's row -> registers (conflict-free via swizzle)
        float4 rr[16];
        #pragma unroll
        for (int j = 0; j < 16; ++j)
            rr[j] = s_cb[(itg << 4) | (j ^ (itg & 15))];
        int v = vstart + tile*TR + itg;

        #pragma unroll
        for (int t = 0; t < 16; ++t) {
            const float4* tk = s_tok + (g*16 + t)*16;
            float ax = 0.f, ay = 0.f, az = 0.f, aw = 0.f;
            #pragma unroll
            for (int j = 0; j < 16; ++j) {
                float4 tv = tk[j];          // warp-uniform broadcast
                ax = fmaf(rr[j].x, tv.x, ax);
                ay = fmaf(rr[j].y, tv.y, ay);
                az = fmaf(rr[j].z, tv.z, az);
                aw = fmaf(rr[j].w, tv.w, aw);
            }
            float d = (ax + ay) + (az + aw);
            if (d > best[t]) { best[t] = d; bidx[t] = v; }   // '>' keeps lowest v
        }
    }

    // reduce across the 128 threads of each token-half (4 warps each)
    int lane = tid & 31, warp = tid >> 5;
    #pragma unroll
    for (int t = 0; t < 16; ++t) {
        float bv = best[t]; int bi = bidx[t];
        #pragma unroll
        for (int off = 16; off > 0; off >>= 1) {
            float ov = __shfl_down_sync(0xffffffffu, bv, off);
            int   oi = __shfl_down_sync(0xffffffffu, bi, off);
            if (ov > bv || (ov == bv && oi < bi)) { bv = ov; bi = oi; }
        }
        if (lane == 0) { sval[warp][t] = bv; sidx[warp][t] = bi; }
    }
    __syncthreads();
    if (tid < 32) {
        int t = tid & 15, gg = tid >> 4;
        float bv = sval[gg*4][t]; int bi = sidx[gg*4][t];
        #pragma unroll
        for (int w = 1; w < 4; ++w) {
            float ov = sval[gg*4 + w][t]; int oi = sidx[gg*4 + w][t];
            if (ov > bv || (ov == bv && oi < bi)) { bv = ov; bi = oi; }
        }
        int tg = t0 + gg*16 + t;
        g_pval[tg*64 + blockIdx.y] = bv;
        g_pidx[tg*64 + blockIdx.y] = bi;
    }
}

// ---------------- reduce vocab splits per token ----------------
__global__ void reduce_kernel(int ntok, int vs) {
    int t = blockIdx.x*256 + threadIdx.x;
    if (t >= ntok) return;
    float bv = g_pval[t*64]; int bi = g_pidx[t*64];
    for (int sp = 1; sp < vs; ++sp) {
        float ov = g_pval[t*64 + sp]; int oi = g_pidx[t*64 + sp];
        if (ov > bv || (ov == bv && oi < bi)) { bv = ov; bi = oi; }
    }
    g_idx[t] = bi;
}

// ---------------- fused gather + upsample + Phi conv + residual update + loss ----------------
#define TL 64
#define PHI_SMEM_FLOATS (CC*(TL+2) + CC*193 + CC)
__global__ void __launch_bounds__(256) phi_update_kernel(
    const float* __restrict__ f, const float* __restrict__ ew,
    const float* __restrict__ phiw, const float* __restrict__ phib,
    int s, int pidx)
{
    extern __shared__ float sm[];
    float* tile = sm;                 // [64][66]
    float* ws   = sm + CC*(TL+2);     // [64][193]
    float* bs   = ws + CC*193;        // [64]

    int b  = blockIdx.x >> 3;
    int l0 = (blockIdx.x & 7) * TL;
    int tid = threadIdx.x;

    const float* wsrc = phiw + pidx*CC*CC*3;
    for (int i = tid; i < CC*192; i += 256) {
        int co = i / 192, rem = i - co*192;
        ws[co*193 + rem] = wsrc[i];
    }
    if (tid < CC) bs[tid] = phib[pidx*CC + tid];

    for (int i = tid; i < CC*(TL+2); i += 256) {
        int ci = i / (TL+2), j = i - ci*(TL+2);
        int l = l0 + j - 1;
        float v = 0.f;
        if (l >= 0 && l < LL) {
            int tokp = (l * s) >> 9;
            int code = g_idx[b*s + tokp];
            v = ew[code*CC + ci];
        }
        tile[ci*(TL+2) + j] = v;
    }
    __syncthreads();

    int co = tid & 63;
    int pbase = (tid >> 6) * 16;
    float acc[16];
    #pragma unroll
    for (int p = 0; p < 16; ++p) acc[p] = 0.f;

    for (int ci = 0; ci < CC; ++ci) {
        const float* wr = ws + co*193 + ci*3;
        float w0 = wr[0], w1 = wr[1], w2 = wr[2];
        const float* hr = tile + ci*(TL+2) + pbase;
        float h[18];
        #pragma unroll
        for (int j = 0; j < 18; ++j) h[j] = hr[j];
        #pragma unroll
        for (int p = 0; p < 16; ++p)
            acc[p] = fmaf(w0, h[p], fmaf(w1, h[p+1], fmaf(w2, h[p+2], acc[p])));
    }

    float ss = 0.f;
    float bb = bs[co];
    #pragma unroll
    for (int p = 0; p < 16; ++p) {
        int l = l0 + pbase + p;
        float hc = tile[co*(TL+2) + pbase + p + 1];
        float y = 0.5f*hc + 0.5f*(acc[p] + bb);
        int gi = (b*CC + co)*LL + l;
        float fh = g_fhat[gi] + y;
        g_fhat[gi] = fh;
        g_frest[gi] -= y;
        float d = fh - f[gi];
        ss = fmaf(d, d, ss);
    }

    #pragma unroll
    for (int off = 16; off > 0; off >>= 1)
        ss += __shfl_xor_sync(0xffffffffu, ss, off);
    __shared__ float red[8];
    int lane = tid & 31, warp = tid >> 5;
    if (lane == 0) red[warp] = ss;
    __syncthreads();
    if (tid == 0) {
        float tot = 0.f;
        #pragma unroll
        for (int w = 0; w < 8; ++w) tot += red[w];
        atomicAdd(&g_loss, tot);
    }
}

// ---------------- finalize: write f_hat and loss ----------------
__global__ void final_kernel(float* __restrict__ out, int out_size) {
    int i = blockIdx.x*256 + threadIdx.x;
    if (i >= out_size) return;
    if (i < NELEM)       out[i] = g_fhat[i];
    else if (i == NELEM) out[i] = g_loss * (1.25f / (10.0f * (float)NELEM));
    else                 out[i] = 0.f;
}

// ---------------- launch ----------------
extern "C" void kernel_launch(void* const* d_in, const int* in_sizes, int n_in,
                              void* d_out, int out_size) {
    // Bind inputs BY ELEMENT COUNT (pairwise distinct -> ordering-immune)
    const float* f    = nullptr;
    const float* ew   = nullptr;
    const float* phiw = nullptr;
    const float* phib = nullptr;
    for (int i = 0; i < n_in; ++i) {
        switch (in_sizes[i]) {
            case 1048576: f    = (const float*)d_in[i]; break;
            case 524288:  ew   = (const float*)d_in[i]; break;
            case 49152:   phiw = (const float*)d_in[i]; break;
            case 256:     phib = (const float*)d_in[i]; break;
            default: break;
        }
    }
    float* out = (float*)d_out;

    const int seg[10] = {1,2,4,8,16,32,64,128,256,512};

    // pmap: bit-exact float64 replication of np.linspace + np.argmin(first-wins)
    int pmap[10];
    {
        double start = 1.0 / 12.0;
        double stop  = 1.0 - 1.0 / 12.0;
        double delta = stop - start;
        double step  = delta / 3.0;
        double ticks[4];
        for (int i = 0; i < 4; ++i) ticks[i] = (double)i * step + start;
        ticks[3] = stop;
        for (int si = 0; si < 10; ++si) {
            double x = (double)si / 9.0;
            int best = 0;
            double bd = fabs(ticks[0] - x);
            for (int i = 1; i < 4; ++i) {
                double d = fabs(ticks[i] - x);
                if (d < bd) { bd = d; best = i; }
            }
            pmap[si] = best;
        }
    }

    cudaFuncSetAttribute(phi_update_kernel,
                         cudaFuncAttributeMaxDynamicSharedMemorySize,
                         PHI_SMEM_FLOATS * (int)sizeof(float));

    normalize_cb_kernel<<<VV, 32>>>(ew);
    init_kernel<<<(NELEM + 255)/256, 256>>>(f);

    for (int si = 0; si < 10; ++si) {
        int s = seg[si];
        int ntok = BB * s;
        int r = LL / s;

        int dtotal = ntok * CC;
        downsample_kernel<<<(dtotal + 255)/256, 256>>>(s, r);
        normalize_tok_kernel<<<(ntok + 7)/8, 256>>>(ntok);

        int vs = VV / ntok;               // widen grid for small scales
        if (vs < 1) vs = 1;
        if (vs > 64) vs = 64;
        int chunk = VV / vs;              // multiple of TR=128 for all vs<=64
        dim3 agrid(ntok / TBTOK, vs);
        argmax_kernel<<<agrid, 256>>>(ntok, chunk);

        reduce_kernel<<<(ntok + 255)/256, 256>>>(ntok, vs);

        phi_update_kernel<<<BB*8, 256, PHI_SMEM_FLOATS*(int)sizeof(float)>>>(
            f, ew, phiw, phib, s, pmap[si]);
    }

    final_kernel<<<(out_size + 255)/256, 256>>>(out, out_size);
}

// round 6
// speedup vs baseline: 7.4335x; 1.0136x over previous
#include <cuda_runtime.h>
#include <math.h>

#define BB 32
#define CC 64
#define LL 512
#define VV 8192
#define NTOK_MAX (BB*LL)      /* 16384 */
#define NELEM (BB*CC*LL)      /* 1048576 */
#define TBTOK 64              /* tokens per argmax block */
#define TR 128                /* codebook rows staged per tile */

// packed f32x2 helpers (sm_100+): lanewise IEEE fma on two packed floats
#define FMA_F32X2(d, a, b, c) \
    asm("fma.rn.f32x2 %0, %1, %2, %3;" : "=l"(d) : "l"(a), "l"(b), "l"(c))
#define UNPACK_F32X2(lo, hi, in) \
    asm("mov.b64 {%0, %1}, %2;" : "=r"(lo), "=r"(hi) : "l"(in))

// ---------------- device scratch (no malloc allowed) ----------------
__device__ float g_cbn[VV*CC];            // normalized codebook, 2MB
__device__ float g_frest[NELEM];          // residual, 4MB
__device__ float g_fhat[NELEM];           // reconstruction, 4MB
__device__ float g_rest_tok[NTOK_MAX*CC]; // downsampled+normalized tokens
__device__ int   g_idx[NTOK_MAX];         // selected codes
__device__ float g_pval[NTOK_MAX*64];     // per-vocab-split partial best val
__device__ int   g_pidx[NTOK_MAX*64];     // per-vocab-split partial best idx
__device__ float g_loss;                  // sum of squared err accum

// ---------------- codebook row-normalize (IEEE sqrt/div, fast-math-proof) ----
__global__ void normalize_cb_kernel(const float* __restrict__ ew) {
    int row = blockIdx.x;
    int lane = threadIdx.x;                 // 32 threads, 2 floats each
    float2 v = reinterpret_cast<const float2*>(ew + row*CC)[lane];
    float ss = v.x*v.x + v.y*v.y;
    #pragma unroll
    for (int off = 16; off > 0; off >>= 1)
        ss += __shfl_xor_sync(0xffffffffu, ss, off);
    float den = fmaxf(__fsqrt_rn(ss), 1e-12f);
    float2 o;
    o.x = __fdiv_rn(v.x, den);
    o.y = __fdiv_rn(v.y, den);
    reinterpret_cast<float2*>(g_cbn + row*CC)[lane] = o;
}

// ---------------- init residual / fhat / loss ----------------
__global__ void init_kernel(const float* __restrict__ f) {
    int i = blockIdx.x*256 + threadIdx.x;
    if (i < NELEM) { g_frest[i] = f[i]; g_fhat[i] = 0.f; }
    if (i == 0) g_loss = 0.f;
}

// ---------- fused area-downsample + row-normalize: warp per token ----------
// lane handles channels (2*lane, 2*lane+1); per-channel sequential sum (same
// order as validated R4/R5 path), scale by exact 1/r, square, butterfly-reduce
// (off 16..1), IEEE sqrt/div.
__global__ void ds_norm_kernel(int s, int r, int ntok) {
    int t = blockIdx.x*8 + (threadIdx.x >> 5);
    if (t >= ntok) return;
    int lane = threadIdx.x & 31;
    int b = t / s, p = t - b*s;
    const float* s0 = g_frest + (b*CC + 2*lane)*LL + p*r;
    const float* s1 = s0 + LL;
    float va = 0.f, vb = 0.f;
    for (int j = 0; j < r; ++j) va += s0[j];
    for (int j = 0; j < r; ++j) vb += s1[j];
    float inv = 1.0f / (float)r;            // r power of two -> exact
    va *= inv; vb *= inv;
    float ss = va*va + vb*vb;
    #pragma unroll
    for (int off = 16; off > 0; off >>= 1)
        ss += __shfl_xor_sync(0xffffffffu, ss, off);
    float den = fmaxf(__fsqrt_rn(ss), 1e-12f);
    float2 o;
    o.x = __fdiv_rn(va, den);
    o.y = __fdiv_rn(vb, den);
    reinterpret_cast<float2*>(g_rest_tok)[t*32 + lane] = o;
}

// ---------------- cosine argmax: 64 tokens/block, FFMA2 inner loop ----------
// 512 threads: thread = row (tid&127) of 128-row codebook tile x 16 tokens of
// its group (g = tid>>7, 4 groups). Packed accumulators (ax,ay),(az,aw) run the
// identical sequential fmaf chains as the validated scalar version; horizontal
// sum (ax+ay)+(az+aw) unchanged -> bit-identical dot products.
__global__ void __launch_bounds__(512) argmax_kernel(int ntok, int chunk, int vs) {
    __shared__ __align__(16) float4 s_tok[TBTOK*16];   // 16KB
    __shared__ __align__(16) float4 s_cb[TR*16];       // 32KB swizzled tile
    __shared__ float  sval[16][16];
    __shared__ int    sidx[16][16];

    int tid = threadIdx.x;
    int t0  = blockIdx.x * TBTOK;

    for (int i = tid; i < TBTOK*16; i += 512) {
        int t = i >> 4, j = i & 15;
        int tg = t0 + t;
        s_tok[i] = (tg < ntok)
                 ? reinterpret_cast<const float4*>(g_rest_tok + tg*CC)[j]
                 : make_float4(0.f, 0.f, 0.f, 0.f);
    }

    int itg = tid & 127;        // row within tile
    int g   = tid >> 7;         // token group (16 tokens each)

    float best[16]; int bidx[16];
    #pragma unroll
    for (int t = 0; t < 16; ++t) { best[t] = -1e30f; bidx[t] = 0; }

    int vstart = blockIdx.y * chunk;
    int ntiles = chunk / TR;

    for (int tile = 0; tile < ntiles; ++tile) {
        __syncthreads();
        const float4* src = reinterpret_cast<const float4*>(g_cbn)
                          + (size_t)(vstart + tile*TR) * 16;
        for (int i = tid; i < TR*16; i += 512) {
            int row = i >> 4, j = i & 15;
            s_cb[(row << 4) | (j ^ (row & 15))] = src[i];
        }
        __syncthreads();

        // this thread's codebook row -> 16 packed-pair registers
        ulonglong2 rrp[16];
        const ulonglong2* cb2 = reinterpret_cast<const ulonglong2*>(s_cb);
        #pragma unroll
        for (int j = 0; j < 16; ++j)
            rrp[j] = cb2[(itg << 4) | (j ^ (itg & 15))];
        int v = vstart + tile*TR + itg;

        #pragma unroll
        for (int t = 0; t < 16; ++t) {
            const ulonglong2* tk =
                reinterpret_cast<const ulonglong2*>(s_tok + (g*16 + t)*16);
            unsigned long long a01 = 0ull, a23 = 0ull;   // (ax,ay),(az,aw)
            #pragma unroll
            for (int j = 0; j < 16; ++j) {
                ulonglong2 tv = tk[j];       // warp-uniform broadcast
                FMA_F32X2(a01, rrp[j].x, tv.x, a01);
                FMA_F32X2(a23, rrp[j].y, tv.y, a23);
            }
            unsigned int uax, uay, uaz, uaw;
            UNPACK_F32X2(uax, uay, a01);
            UNPACK_F32X2(uaz, uaw, a23);
            float d = (__uint_as_float(uax) + __uint_as_float(uay))
                    + (__uint_as_float(uaz) + __uint_as_float(uaw));
            if (d > best[t]) { best[t] = d; bidx[t] = v; }   // '>' keeps lowest v
        }
    }

    int lane = tid & 31, warp = tid >> 5;   // 16 warps; group g owns warps 4g..4g+3
    #pragma unroll
    for (int t = 0; t < 16; ++t) {
        float bv = best[t]; int bi = bidx[t];
        #pragma unroll
        for (int off = 16; off > 0; off >>= 1) {
            float ov = __shfl_down_sync(0xffffffffu, bv, off);
            int   oi = __shfl_down_sync(0xffffffffu, bi, off);
            if (ov > bv || (ov == bv && oi < bi)) { bv = ov; bi = oi; }
        }
        if (lane == 0) { sval[warp][t] = bv; sidx[warp][t] = bi; }
    }
    __syncthreads();
    if (tid < 64) {
        int t = tid & 15, gg = tid >> 4;
        float bv = sval[gg*4][t]; int bi = sidx[gg*4][t];
        #pragma unroll
        for (int w = 1; w < 4; ++w) {
            float ov = sval[gg*4 + w][t]; int oi = sidx[gg*4 + w][t];
            if (ov > bv || (ov == bv && oi < bi)) { bv = ov; bi = oi; }
        }
        int tg = t0 + gg*16 + t;
        if (tg < ntok) {
            if (vs == 1) g_idx[tg] = bi;
            else { g_pval[tg*64 + blockIdx.y] = bv; g_pidx[tg*64 + blockIdx.y] = bi; }
        }
    }
}

// ---------------- reduce vocab splits per token (vs>1 only) ----------------
__global__ void reduce_kernel(int ntok, int vs) {
    int t = blockIdx.x*256 + threadIdx.x;
    if (t >= ntok) return;
    float bv = g_pval[t*64]; int bi = g_pidx[t*64];
    for (int sp = 1; sp < vs; ++sp) {
        float ov = g_pval[t*64 + sp]; int oi = g_pidx[t*64 + sp];
        if (ov > bv || (ov == bv && oi < bi)) { bv = ov; bi = oi; }
    }
    g_idx[t] = bi;
}

// ---------------- fused gather + upsample + Phi conv + residual update + loss ----------------
#define TL 64
#define PHI_SMEM_FLOATS (CC*(TL+2) + CC*193 + CC)
__global__ void __launch_bounds__(256) phi_update_kernel(
    const float* __restrict__ f, const float* __restrict__ ew,
    const float* __restrict__ phiw, const float* __restrict__ phib,
    int s, int pidx, float* __restrict__ outp)
{
    extern __shared__ float sm[];
    float* tile = sm;                 // [64][66]
    float* ws   = sm + CC*(TL+2);     // [64][193]
    float* bs   = ws + CC*193;        // [64]

    int b  = blockIdx.x >> 3;
    int l0 = (blockIdx.x & 7) * TL;
    int tid = threadIdx.x;

    const float* wsrc = phiw + pidx*CC*CC*3;
    for (int i = tid; i < CC*192; i += 256) {
        int co = i / 192, rem = i - co*192;
        ws[co*193 + rem] = wsrc[i];
    }
    if (tid < CC) bs[tid] = phib[pidx*CC + tid];

    for (int i = tid; i < CC*(TL+2); i += 256) {
        int ci = i / (TL+2), j = i - ci*(TL+2);
        int l = l0 + j - 1;
        float v = 0.f;
        if (l >= 0 && l < LL) {
            int tokp = (l * s) >> 9;
            int code = g_idx[b*s + tokp];
            v = ew[code*CC + ci];
        }
        tile[ci*(TL+2) + j] = v;
    }
    __syncthreads();

    int co = tid & 63;
    int pbase = (tid >> 6) * 16;
    float acc[16];
    #pragma unroll
    for (int p = 0; p < 16; ++p) acc[p] = 0.f;

    for (int ci = 0; ci < CC; ++ci) {
        const float* wr = ws + co*193 + ci*3;
        float w0 = wr[0], w1 = wr[1], w2 = wr[2];
        const float* hr = tile + ci*(TL+2) + pbase;
        float h[18];
        #pragma unroll
        for (int j = 0; j < 18; ++j) h[j] = hr[j];
        #pragma unroll
        for (int p = 0; p < 16; ++p)
            acc[p] = fmaf(w0, h[p], fmaf(w1, h[p+1], fmaf(w2, h[p+2], acc[p])));
    }

    float ss = 0.f;
    float bb = bs[co];
    #pragma unroll
    for (int p = 0; p < 16; ++p) {
        int l = l0 + pbase + p;
        float hc = tile[co*(TL+2) + pbase + p + 1];
        float y = 0.5f*hc + 0.5f*(acc[p] + bb);
        int gi = (b*CC + co)*LL + l;
        float fh = g_fhat[gi] + y;
        if (outp) {
            outp[gi] = fh;                 // last scale: write output directly
        } else {
            g_fhat[gi] = fh;
            g_frest[gi] -= y;
        }
        float d = fh - f[gi];
        ss = fmaf(d, d, ss);
    }

    #pragma unroll
    for (int off = 16; off > 0; off >>= 1)
        ss += __shfl_xor_sync(0xffffffffu, ss, off);
    __shared__ float red[8];
    int lane = tid & 31, warp = tid >> 5;
    if (lane == 0) red[warp] = ss;
    __syncthreads();
    if (tid == 0) {
        float tot = 0.f;
        #pragma unroll
        for (int w = 0; w < 8; ++w) tot += red[w];
        atomicAdd(&g_loss, tot);
    }
}

// ---------------- tail: loss scalar (+ zero any padding) ----------------
__global__ void loss_kernel(float* __restrict__ out, int out_size) {
    int i = NELEM + blockIdx.x*256 + threadIdx.x;
    if (i >= out_size) return;
    out[i] = (i == NELEM) ? g_loss * (1.25f / (10.0f * (float)NELEM)) : 0.f;
}

// ---------------- launch ----------------
extern "C" void kernel_launch(void* const* d_in, const int* in_sizes, int n_in,
                              void* d_out, int out_size) {
    // Bind inputs BY ELEMENT COUNT (pairwise distinct -> ordering-immune)
    const float* f    = nullptr;
    const float* ew   = nullptr;
    const float* phiw = nullptr;
    const float* phib = nullptr;
    for (int i = 0; i < n_in; ++i) {
        switch (in_sizes[i]) {
            case 1048576: f    = (const float*)d_in[i]; break;
            case 524288:  ew   = (const float*)d_in[i]; break;
            case 49152:   phiw = (const float*)d_in[i]; break;
            case 256:     phib = (const float*)d_in[i]; break;
            default: break;
        }
    }
    float* out = (float*)d_out;

    const int seg[10] = {1,2,4,8,16,32,64,128,256,512};

    // pmap: bit-exact float64 replication of np.linspace + np.argmin(first-wins)
    int pmap[10];
    {
        double start = 1.0 / 12.0;
        double stop  = 1.0 - 1.0 / 12.0;
        double delta = stop - start;
        double step  = delta / 3.0;
        double ticks[4];
        for (int i = 0; i < 4; ++i) ticks[i] = (double)i * step + start;
        ticks[3] = stop;
        for (int si = 0; si < 10; ++si) {
            double x = (double)si / 9.0;
            int best = 0;
            double bd = fabs(ticks[0] - x);
            for (int i = 1; i < 4; ++i) {
                double d = fabs(ticks[i] - x);
                if (d < bd) { bd = d; best = i; }
            }
            pmap[si] = best;
        }
    }

    cudaFuncSetAttribute(phi_update_kernel,
                         cudaFuncAttributeMaxDynamicSharedMemorySize,
                         PHI_SMEM_FLOATS * (int)sizeof(float));

    normalize_cb_kernel<<<VV, 32>>>(ew);
    init_kernel<<<(NELEM + 255)/256, 256>>>(f);

    for (int si = 0; si < 10; ++si) {
        int s = seg[si];
        int ntok = BB * s;
        int r = LL / s;

        ds_norm_kernel<<<(ntok + 7)/8, 256>>>(s, r, ntok);

        int vs = 16384 / ntok;            // pow2; targets >=148 blocks
        if (vs < 1) vs = 1;
        if (vs > 64) vs = 64;
        int chunk = VV / vs;              // multiple of TR=128
        dim3 agrid((ntok + TBTOK - 1)/TBTOK, vs);
        argmax_kernel<<<agrid, 512>>>(ntok, chunk, vs);

        if (vs > 1)
            reduce_kernel<<<(ntok + 255)/256, 256>>>(ntok, vs);

        phi_update_kernel<<<BB*8, 256, PHI_SMEM_FLOATS*(int)sizeof(float)>>>(
            f, ew, phiw, phib, s, pmap[si], (si == 9) ? out : nullptr);
    }

    loss_kernel<<<(out_size - NELEM + 255)/256, 256>>>(out, out_size);
}